// round 3
// baseline (speedup 1.0000x reference)
#include <cuda_runtime.h>
#include <cuda.h>
#include <cstdint>

// ---------------------------------------------------------------------------
// Problem constants
// ---------------------------------------------------------------------------
#define BB 4
#define HH 224
#define WW 224
#define HW (HH * WW)                 // 50176
#define NPLANE 128                   // B*C
#define NTOT ((size_t)NPLANE * HW)   // 6,422,528 floats

#define ST 4            // steps per pipeline stage
#define NS 3            // pipeline stages
#define NGRP (HH / ST)  // 56 groups
#define STAGE_BYTES (4 * ST * 224 * 4)  // 14336 B per stage (4 arrays)

// Scratch (no cudaMalloc allowed). 256B-aligned for TMA/bulk.
__device__ __align__(256) float g_x[NTOT];
__device__ __align__(256) float g_dir[4 * NTOT];

// ---------------------------------------------------------------------------
// PTX helpers
// ---------------------------------------------------------------------------
__device__ __forceinline__ uint32_t s2u(const void* p) {
    return (uint32_t)__cvta_generic_to_shared(p);
}
__device__ __forceinline__ void mbar_init(uint32_t a, uint32_t cnt) {
    asm volatile("mbarrier.init.shared.b64 [%0], %1;" ::"r"(a), "r"(cnt)
                 : "memory");
}
__device__ __forceinline__ void mbar_expect(uint32_t a, uint32_t tx) {
    asm volatile("mbarrier.arrive.expect_tx.shared.b64 _, [%0], %1;" ::"r"(a),
                 "r"(tx)
                 : "memory");
}
__device__ __forceinline__ void mbar_wait(uint32_t a, uint32_t ph) {
    asm volatile(
        "{\n\t.reg .pred P%=;\n"
        "W%=:\n\t"
        "mbarrier.try_wait.parity.acquire.cta.shared::cta.b64 P%=, [%0], %1, "
        "0x989680;\n\t"
        "@P%= bra D%=;\n\t"
        "bra W%=;\n"
        "D%=:\n\t}" ::"r"(a),
        "r"(ph)
        : "memory");
}
__device__ __forceinline__ void fence_async() {
    asm volatile("fence.proxy.async.shared::cta;" ::: "memory");
}
__device__ __forceinline__ void tma4(float* dst, const CUtensorMap* tm, int c0,
                                     int c1, int c2, int c3, uint32_t bar) {
    asm volatile(
        "cp.async.bulk.tensor.4d.shared::cta.global.tile.mbarrier::complete_tx"
        "::bytes [%0], [%1, {%2,%3,%4,%5}], [%6];" ::"r"(s2u(dst)),
        "l"(tm), "r"(c0), "r"(c1), "r"(c2), "r"(c3), "r"(bar)
        : "memory");
}
__device__ __forceinline__ void tma3(float* dst, const CUtensorMap* tm, int c0,
                                     int c1, int c2, uint32_t bar) {
    asm volatile(
        "cp.async.bulk.tensor.3d.shared::cta.global.tile.mbarrier::complete_tx"
        "::bytes [%0], [%1, {%2,%3,%4}], [%5];" ::"r"(s2u(dst)),
        "l"(tm), "r"(c0), "r"(c1), "r"(c2), "r"(bar)
        : "memory");
}
// cp.async fallback helpers
__device__ __forceinline__ void cpa16(float* dst, const float* src) {
    asm volatile("cp.async.cg.shared.global [%0], [%1], 16;" ::"r"(s2u(dst)),
                 "l"(src));
}
__device__ __forceinline__ void cpa_commit() {
    asm volatile("cp.async.commit_group;");
}
__device__ __forceinline__ void cpa_wait2() {
    asm volatile("cp.async.wait_group 2;");
}

// ---------------------------------------------------------------------------
// K0: conv2d 3x3 same, 2 -> 32, writes g_x
// ---------------------------------------------------------------------------
__global__ void conv_in_kernel(const float* __restrict__ y,
                               const float* __restrict__ w3) {
    __shared__ float ws[576];
    for (int i = threadIdx.x; i < 576; i += blockDim.x) ws[i] = w3[i];
    __syncthreads();

    int idx = blockIdx.x * blockDim.x + threadIdx.x;
    if (idx >= BB * HW) return;
    int b = idx / HW, pix = idx - b * HW;
    int py = pix / WW, px = pix - py * WW;

    float in[2][3][3];
#pragma unroll
    for (int ic = 0; ic < 2; ic++)
#pragma unroll
        for (int ky = 0; ky < 3; ky++)
#pragma unroll
            for (int kx = 0; kx < 3; kx++) {
                int yy = py + ky - 1, xx = px + kx - 1;
                bool v = ((unsigned)yy < HH) && ((unsigned)xx < WW);
                in[ic][ky][kx] =
                    v ? __ldg(y + ((size_t)(b * 2 + ic)) * HW + yy * WW + xx)
                      : 0.0f;
            }

    for (int oc = 0; oc < 32; oc++) {
        float a = 0.0f;
#pragma unroll
        for (int ic = 0; ic < 2; ic++)
#pragma unroll
            for (int k = 0; k < 9; k++)
                a += in[ic][k / 3][k % 3] * ws[(oc * 2 + ic) * 9 + k];
        g_x[((size_t)(b * 32 + oc)) * HW + pix] = a;
    }
}

// ---------------------------------------------------------------------------
// TMA scan body.
//   sbuf stage layout (matches TMA box write order):
//     vertical  box {224,4}: sbuf[a][r*224 + s], chunk row r (fwd: r=j, rev: r=3-j)
//     horizontal box {4,224}: sbuf[a][s*4 + c]  (fwd: c=j, rev: c=3-j)
// ---------------------------------------------------------------------------
template <bool HOR, bool REV>
__device__ void scan_tma_body(const CUtensorMap* tg4, const CUtensorMap* tx3,
                              int ch0, int b, int plane,
                              float* __restrict__ yp,
                              float (*sbuf)[4][ST * 224], float (*hbuf)[226],
                              uint64_t* mbar, int s) {
    auto fill = [&](int st, int tg) {
        uint32_t bar = s2u(&mbar[st]);
        mbar_expect(bar, STAGE_BYTES);
        int base = REV ? 220 - 4 * tg : 4 * tg;
        int c0 = HOR ? base : 0;
        int c1 = HOR ? 0 : base;
        tma4(&sbuf[st][0][0], tg4, c0, c1, ch0, b, bar);
        tma4(&sbuf[st][1][0], tg4, c0, c1, ch0 + 32, b, bar);
        tma4(&sbuf[st][2][0], tg4, c0, c1, ch0 + 64, b, bar);
        tma3(&sbuf[st][3][0], tx3, c0, c1, plane, bar);
    };

    if (s == 0) {
        fence_async();
        fill(0, 0);
        fill(1, 1);
        fill(2, 2);
    }

    int cur = 0;
    float hown = 0.0f;

    for (int tg = 0; tg < NGRP; tg++) {
        int st = tg % NS;
        int ph = (tg / NS) & 1;
        mbar_wait(s2u(&mbar[st]), (uint32_t)ph);

        // Off-chain: normalize gates + premultiply x for all ST steps.
        float a1[ST], a2[ST], a3[ST], cx[ST];
        if (HOR) {
            float4 G1 = *(const float4*)&sbuf[st][0][s * 4];
            float4 G2 = *(const float4*)&sbuf[st][1][s * 4];
            float4 G3 = *(const float4*)&sbuf[st][2][s * 4];
            float4 Xv = *(const float4*)&sbuf[st][3][s * 4];
            float b1[4] = {G1.x, G1.y, G1.z, G1.w};
            float b2[4] = {G2.x, G2.y, G2.z, G2.w};
            float b3[4] = {G3.x, G3.y, G3.z, G3.w};
            float bx[4] = {Xv.x, Xv.y, Xv.z, Xv.w};
#pragma unroll
            for (int j = 0; j < ST; j++) {
                int c = REV ? 3 - j : j;
                float inv = __fdividef(
                    1.0f,
                    fmaxf(fabsf(b1[c]) + fabsf(b2[c]) + fabsf(b3[c]), 1.0f));
                a1[j] = b1[c] * inv;
                a2[j] = b2[c] * inv;
                a3[j] = b3[c] * inv;
                cx[j] = (1.0f - a1[j] - a2[j] - a3[j]) * bx[c];
            }
        } else {
#pragma unroll
            for (int j = 0; j < ST; j++) {
                int r = REV ? 3 - j : j;
                float G1 = sbuf[st][0][r * 224 + s];
                float G2 = sbuf[st][1][r * 224 + s];
                float G3 = sbuf[st][2][r * 224 + s];
                float X = sbuf[st][3][r * 224 + s];
                float inv = __fdividef(
                    1.0f, fmaxf(fabsf(G1) + fabsf(G2) + fabsf(G3), 1.0f));
                a1[j] = G1 * inv;
                a2[j] = G2 * inv;
                a3[j] = G3 * inv;
                cx[j] = (1.0f - a1[j] - a2[j] - a3[j]) * X;
            }
        }

        // Serial recurrence steps.
        float hv[ST];
#pragma unroll
        for (int j = 0; j < ST; j++) {
            float hl = hbuf[cur][s];
            float hr = hbuf[cur][s + 2];
            float hn =
                fmaf(a1[j], hl, fmaf(a2[j], hown, fmaf(a3[j], hr, cx[j])));
            hbuf[cur ^ 1][s + 1] = hn;
            hown = hn;
            hv[j] = hn;
            cur ^= 1;
            __syncthreads();
            if (!HOR) {
                int row = REV ? 223 - (4 * tg + j) : 4 * tg + j;
                yp[row * WW + s] = hn;  // coalesced
            }
        }
        if (HOR) {
            int base = REV ? 220 - 4 * tg : 4 * tg;
            float4 o;
            if (REV) { o.x = hv[3]; o.y = hv[2]; o.z = hv[1]; o.w = hv[0]; }
            else     { o.x = hv[0]; o.y = hv[1]; o.z = hv[2]; o.w = hv[3]; }
            *(float4*)(yp + s * WW + base) = o;
        }

        int nt = tg + NS;
        if (s == 0 && nt < NGRP) fill(st, nt);
    }
}

__global__ void __launch_bounds__(224) scan_kernel_tma(
    const __grid_constant__ CUtensorMap tmg_h,
    const __grid_constant__ CUtensorMap tmg_v,
    const __grid_constant__ CUtensorMap tmx_h,
    const __grid_constant__ CUtensorMap tmx_v) {
    __shared__ __align__(128) float sbuf[NS][4][ST * 224];  // 43008 B
    __shared__ float hbuf[2][226];
    __shared__ __align__(8) uint64_t mbar[NS];

    int s = threadIdx.x;
    int plane = blockIdx.x;
    int d = blockIdx.y;
    int b = plane >> 5, c = plane & 31;
    int ch0 = 96 * d + c;

    float* yp = g_dir + (size_t)d * NTOT + (size_t)plane * HW;

    if (s == 0) {
        mbar_init(s2u(&mbar[0]), 1);
        mbar_init(s2u(&mbar[1]), 1);
        mbar_init(s2u(&mbar[2]), 1);
    }
    hbuf[0][s + 1] = 0.0f;
    if (s < 2) { hbuf[0][s * 225] = 0.0f; hbuf[1][s * 225] = 0.0f; }
    __syncthreads();

    switch (d) {
        case 0:
            scan_tma_body<true, false>(&tmg_h, &tmx_h, ch0, b, plane, yp, sbuf,
                                       hbuf, mbar, s);
            break;
        case 1:
            scan_tma_body<false, true>(&tmg_v, &tmx_v, ch0, b, plane, yp, sbuf,
                                       hbuf, mbar, s);
            break;
        case 2:
            scan_tma_body<false, false>(&tmg_v, &tmx_v, ch0, b, plane, yp,
                                        sbuf, hbuf, mbar, s);
            break;
        default:
            scan_tma_body<true, true>(&tmg_h, &tmx_h, ch0, b, plane, yp, sbuf,
                                      hbuf, mbar, s);
            break;
    }
}

// ---------------------------------------------------------------------------
// Fallback scan (R2 cp.async version) — used only if driver entry point for
// tensor-map encoding cannot be resolved.
// ---------------------------------------------------------------------------
template <bool HOR, bool REV>
__device__ void scan_pipe_fb(const float* __restrict__ g1p,
                             const float* __restrict__ g2p,
                             const float* __restrict__ g3p,
                             const float* __restrict__ xp,
                             float* __restrict__ yp,
                             float (*sbuf)[4][ST * 224], float (*hbuf)[226],
                             int s) {
    const float* garr[4] = {g1p, g2p, g3p, xp};
    auto fill = [&](int st, int tg) {
        if (HOR) {
            int base = REV ? 220 - 4 * tg : 4 * tg;
#pragma unroll
            for (int a = 0; a < 4; a++)
                cpa16(&sbuf[st][a][s * 4], garr[a] + s * WW + base);
        } else {
            int j = s / 56, q = s - j * 56;
            int row = REV ? 223 - (4 * tg + j) : 4 * tg + j;
#pragma unroll
            for (int a = 0; a < 4; a++)
                cpa16(&sbuf[st][a][j * 224 + q * 4],
                      garr[a] + row * WW + q * 4);
        }
    };
#pragma unroll
    for (int p = 0; p < NS; p++) { fill(p, p); cpa_commit(); }
    int cur = 0;
    float hown = 0.0f;
    for (int tg = 0; tg < NGRP; tg++) {
        int st = tg % NS;
        cpa_wait2();
        __syncthreads();
        float a1[ST], a2[ST], a3[ST], cx[ST];
        if (HOR) {
            float4 G1 = *(const float4*)&sbuf[st][0][s * 4];
            float4 G2 = *(const float4*)&sbuf[st][1][s * 4];
            float4 G3 = *(const float4*)&sbuf[st][2][s * 4];
            float4 Xv = *(const float4*)&sbuf[st][3][s * 4];
            float b1[4] = {G1.x, G1.y, G1.z, G1.w};
            float b2[4] = {G2.x, G2.y, G2.z, G2.w};
            float b3[4] = {G3.x, G3.y, G3.z, G3.w};
            float bx[4] = {Xv.x, Xv.y, Xv.z, Xv.w};
#pragma unroll
            for (int j = 0; j < ST; j++) {
                int c = REV ? 3 - j : j;
                float inv = __fdividef(
                    1.0f,
                    fmaxf(fabsf(b1[c]) + fabsf(b2[c]) + fabsf(b3[c]), 1.0f));
                a1[j] = b1[c] * inv; a2[j] = b2[c] * inv; a3[j] = b3[c] * inv;
                cx[j] = (1.0f - a1[j] - a2[j] - a3[j]) * bx[c];
            }
        } else {
#pragma unroll
            for (int j = 0; j < ST; j++) {
                float G1 = sbuf[st][0][j * 224 + s];
                float G2 = sbuf[st][1][j * 224 + s];
                float G3 = sbuf[st][2][j * 224 + s];
                float X = sbuf[st][3][j * 224 + s];
                float inv = __fdividef(
                    1.0f, fmaxf(fabsf(G1) + fabsf(G2) + fabsf(G3), 1.0f));
                a1[j] = G1 * inv; a2[j] = G2 * inv; a3[j] = G3 * inv;
                cx[j] = (1.0f - a1[j] - a2[j] - a3[j]) * X;
            }
        }
        float hv[ST];
#pragma unroll
        for (int j = 0; j < ST; j++) {
            float hl = hbuf[cur][s];
            float hr = hbuf[cur][s + 2];
            float hn =
                fmaf(a1[j], hl, fmaf(a2[j], hown, fmaf(a3[j], hr, cx[j])));
            hbuf[cur ^ 1][s + 1] = hn;
            hown = hn; hv[j] = hn; cur ^= 1;
            __syncthreads();
            if (!HOR) {
                int row = REV ? 223 - (4 * tg + j) : 4 * tg + j;
                yp[row * WW + s] = hn;
            }
        }
        if (HOR) {
            int base = REV ? 220 - 4 * tg : 4 * tg;
            float4 o;
            if (REV) { o.x = hv[3]; o.y = hv[2]; o.z = hv[1]; o.w = hv[0]; }
            else     { o.x = hv[0]; o.y = hv[1]; o.z = hv[2]; o.w = hv[3]; }
            *(float4*)(yp + s * WW + base) = o;
        }
        int nt = tg + NS;
        if (nt < NGRP) fill(st, nt);
        cpa_commit();
    }
}

__global__ void __launch_bounds__(224) scan_kernel_fb(
    const float* __restrict__ gates) {
    __shared__ float sbuf[NS][4][ST * 224];
    __shared__ float hbuf[2][226];
    int s = threadIdx.x;
    int plane = blockIdx.x;
    int d = blockIdx.y;
    int b = plane >> 5, c = plane & 31;
    const float* gp = gates + ((size_t)b * 384 + (size_t)(3 * d) * 32 + c) * HW;
    const float* g1p = gp;
    const float* g2p = gp + (size_t)32 * HW;
    const float* g3p = gp + (size_t)64 * HW;
    const float* xp = g_x + (size_t)plane * HW;
    float* yp = g_dir + (size_t)d * NTOT + (size_t)plane * HW;
    hbuf[0][s + 1] = 0.0f;
    if (s < 2) { hbuf[0][s * 225] = 0.0f; hbuf[1][s * 225] = 0.0f; }
    __syncthreads();
    switch (d) {
        case 0:  scan_pipe_fb<true,  false>(g1p, g2p, g3p, xp, yp, sbuf, hbuf, s); break;
        case 1:  scan_pipe_fb<false, true >(g1p, g2p, g3p, xp, yp, sbuf, hbuf, s); break;
        case 2:  scan_pipe_fb<false, false>(g1p, g2p, g3p, xp, yp, sbuf, hbuf, s); break;
        default: scan_pipe_fb<true,  true >(g1p, g2p, g3p, xp, yp, sbuf, hbuf, s); break;
    }
}

// ---------------------------------------------------------------------------
// Combine: g_x = elementwise max over the 4 direction buffers (float4).
// ---------------------------------------------------------------------------
__global__ void combine_kernel() {
    const size_t n4 = NTOT / 4;
    const float4* p0 = (const float4*)g_dir;
    const float4* p1 = (const float4*)(g_dir + NTOT);
    const float4* p2 = (const float4*)(g_dir + 2 * NTOT);
    const float4* p3 = (const float4*)(g_dir + 3 * NTOT);
    float4* o = (float4*)g_x;
    for (size_t i = blockIdx.x * (size_t)blockDim.x + threadIdx.x; i < n4;
         i += (size_t)gridDim.x * blockDim.x) {
        float4 a = __ldg(p0 + i), b = __ldg(p1 + i);
        float4 c = __ldg(p2 + i), d = __ldg(p3 + i);
        float4 r;
        r.x = fmaxf(fmaxf(a.x, b.x), fmaxf(c.x, d.x));
        r.y = fmaxf(fmaxf(a.y, b.y), fmaxf(c.y, d.y));
        r.z = fmaxf(fmaxf(a.z, b.z), fmaxf(c.z, d.z));
        r.w = fmaxf(fmaxf(a.w, b.w), fmaxf(c.w, d.w));
        o[i] = r;
    }
}

// ---------------------------------------------------------------------------
// K3: conv2d 3x3 same 32 -> 2 on g_x, fused log_softmax over the 2 channels.
// ---------------------------------------------------------------------------
__global__ void conv_out_kernel(const float* __restrict__ w4,
                                float* __restrict__ out) {
    __shared__ float ws[576];
    for (int i = threadIdx.x; i < 576; i += blockDim.x) ws[i] = w4[i];
    __syncthreads();

    int idx = blockIdx.x * blockDim.x + threadIdx.x;
    if (idx >= BB * HW) return;
    int b = idx / HW, pix = idx - b * HW;
    int py = pix / WW, px = pix - py * WW;

    float a0 = 0.0f, a1 = 0.0f;
    for (int ic = 0; ic < 32; ic++) {
        const float* ip = g_x + ((size_t)(b * 32 + ic)) * HW;
#pragma unroll
        for (int ky = 0; ky < 3; ky++) {
            int yy = py + ky - 1;
            bool vy = (unsigned)yy < HH;
#pragma unroll
            for (int kx = 0; kx < 3; kx++) {
                int xx = px + kx - 1;
                float v = (vy && (unsigned)xx < WW)
                              ? __ldg(ip + yy * WW + xx)
                              : 0.0f;
                int wi = ic * 9 + ky * 3 + kx;
                a0 += v * ws[wi];
                a1 += v * ws[288 + wi];
            }
        }
    }
    float m = fmaxf(a0, a1);
    float l = m + logf(expf(a0 - m) + expf(a1 - m));
    out[(size_t)(b * 2) * HW + pix] = a0 - l;
    out[(size_t)(b * 2 + 1) * HW + pix] = a1 - l;
}

// ---------------------------------------------------------------------------
// Host: resolve cuTensorMapEncodeTiled via runtime (no -lcuda link needed),
// build 4 tensor maps, launch the pipeline.
// ---------------------------------------------------------------------------
typedef CUresult (*tmEncodeFn)(CUtensorMap*, CUtensorMapDataType, cuuint32_t,
                               void*, const cuuint64_t*, const cuuint64_t*,
                               const cuuint32_t*, const cuuint32_t*,
                               CUtensorMapInterleave, CUtensorMapSwizzle,
                               CUtensorMapL2promotion, CUtensorMapFloatOOBfill);

static tmEncodeFn resolve_encoder() {
    void* fn = nullptr;
    cudaDriverEntryPointQueryResult st;
#if CUDART_VERSION >= 12050
    if (cudaGetDriverEntryPointByVersion("cuTensorMapEncodeTiled", &fn, 12000,
                                         cudaEnableDefault,
                                         &st) == cudaSuccess &&
        fn)
        return (tmEncodeFn)fn;
    fn = nullptr;
#else
    if (cudaGetDriverEntryPoint("cuTensorMapEncodeTiled", &fn,
                                cudaEnableDefault, &st) == cudaSuccess &&
        fn)
        return (tmEncodeFn)fn;
#endif
    return nullptr;
}

extern "C" void kernel_launch(void* const* d_in, const int* in_sizes, int n_in,
                              void* d_out, int out_size) {
    const float* gates = (const float*)d_in[0];
    const float* y     = (const float*)d_in[1];
    const float* w3    = (const float*)d_in[2];
    const float* w4    = (const float*)d_in[3];
    float* out = (float*)d_out;

    int pxblocks = (BB * HW + 255) / 256;
    dim3 sg(NPLANE, 4);

    // Build tensor maps
    bool use_tma = false;
    CUtensorMap tg_h, tg_v, tx_h, tx_v;
    tmEncodeFn enc = resolve_encoder();
    void* xaddr = nullptr;
    cudaGetSymbolAddress(&xaddr, g_x);
    if (enc && xaddr) {
        cuuint64_t gd4[4] = {224, 224, 384, 4};
        cuuint64_t gs4[3] = {896, 200704, 200704ULL * 384};
        cuuint64_t gd3[3] = {224, 224, 128};
        cuuint64_t gs3[2] = {896, 200704};
        cuuint32_t bh4[4] = {4, 224, 1, 1}, bv4[4] = {224, 4, 1, 1};
        cuuint32_t bh3[3] = {4, 224, 1}, bv3[3] = {224, 4, 1};
        cuuint32_t es[4] = {1, 1, 1, 1};
        CUresult r = CUDA_SUCCESS;
        r = enc(&tg_h, CU_TENSOR_MAP_DATA_TYPE_FLOAT32, 4, (void*)gates, gd4,
                gs4, bh4, es, CU_TENSOR_MAP_INTERLEAVE_NONE,
                CU_TENSOR_MAP_SWIZZLE_NONE, CU_TENSOR_MAP_L2_PROMOTION_L2_128B,
                CU_TENSOR_MAP_FLOAT_OOB_FILL_NONE);
        if (r == CUDA_SUCCESS)
            r = enc(&tg_v, CU_TENSOR_MAP_DATA_TYPE_FLOAT32, 4, (void*)gates,
                    gd4, gs4, bv4, es, CU_TENSOR_MAP_INTERLEAVE_NONE,
                    CU_TENSOR_MAP_SWIZZLE_NONE,
                    CU_TENSOR_MAP_L2_PROMOTION_L2_128B,
                    CU_TENSOR_MAP_FLOAT_OOB_FILL_NONE);
        if (r == CUDA_SUCCESS)
            r = enc(&tx_h, CU_TENSOR_MAP_DATA_TYPE_FLOAT32, 3, xaddr, gd3, gs3,
                    bh3, es, CU_TENSOR_MAP_INTERLEAVE_NONE,
                    CU_TENSOR_MAP_SWIZZLE_NONE,
                    CU_TENSOR_MAP_L2_PROMOTION_L2_128B,
                    CU_TENSOR_MAP_FLOAT_OOB_FILL_NONE);
        if (r == CUDA_SUCCESS)
            r = enc(&tx_v, CU_TENSOR_MAP_DATA_TYPE_FLOAT32, 3, xaddr, gd3, gs3,
                    bv3, es, CU_TENSOR_MAP_INTERLEAVE_NONE,
                    CU_TENSOR_MAP_SWIZZLE_NONE,
                    CU_TENSOR_MAP_L2_PROMOTION_L2_128B,
                    CU_TENSOR_MAP_FLOAT_OOB_FILL_NONE);
        use_tma = (r == CUDA_SUCCESS);
    }

    conv_in_kernel<<<pxblocks, 256>>>(y, w3);
    if (use_tma) {
        scan_kernel_tma<<<sg, 224>>>(tg_h, tg_v, tx_h, tx_v);
        combine_kernel<<<2048, 256>>>();
        scan_kernel_tma<<<sg, 224>>>(tg_h, tg_v, tx_h, tx_v);
    } else {
        scan_kernel_fb<<<sg, 224>>>(gates);
        combine_kernel<<<2048, 256>>>();
        scan_kernel_fb<<<sg, 224>>>(gates);
    }
    combine_kernel<<<2048, 256>>>();
    conv_out_kernel<<<pxblocks, 256>>>(w4, out);
}

// round 5
// speedup vs baseline: 1.1203x; 1.1203x over previous
#include <cuda_runtime.h>
#include <cstdint>

// ---------------------------------------------------------------------------
// Problem constants
// ---------------------------------------------------------------------------
#define BB 4
#define HH 224
#define WW 224
#define HW (HH * WW)                 // 50176
#define NPLANE 128                   // B*C
#define NTOT ((size_t)NPLANE * HW)   // 6,422,528 floats

#define ST 4                    // steps per pipeline stage
#define NS 3                    // pipeline stages
#define NGRP (HH / ST)          // 56 groups
#define STAGEF (4 * ST * 224)   // floats per stage per warp = 3584
#define ABYTES (ST * 224 * 4)   // bytes per array within a stage = 3584
#define WARPF (NS * STAGEF)     // floats per warp = 10752
#define SMEM_BYTES (4 * WARPF * 4)  // 172032 B per block (4 warps)

// Scratch (no cudaMalloc allowed)
__device__ __align__(256) float g_x[NTOT];
__device__ __align__(256) float g_dir[4 * NTOT];

// ---------------------------------------------------------------------------
// cp.async helpers
// ---------------------------------------------------------------------------
__device__ __forceinline__ uint32_t s2u(const void* p) {
    return (uint32_t)__cvta_generic_to_shared(p);
}
__device__ __forceinline__ void cpa16(uint32_t dst, const float* src) {
    asm volatile("cp.async.cg.shared.global [%0], [%1], 16;" ::"r"(dst),
                 "l"(src));
}
__device__ __forceinline__ void cpa_commit() {
    asm volatile("cp.async.commit_group;");
}
__device__ __forceinline__ void cpa_waitN() {
    asm volatile("cp.async.wait_group %0;" ::"n"(NS - 1));
}

// 128B-line chunk swizzle (16B granularity): breaks LDS bank conflicts for the
// horizontal stage layout. Applied identically by producer and consumer.
__device__ __forceinline__ uint32_t swz(uint32_t byte_off) {
    return byte_off ^ ((byte_off >> 3) & 0x70);
}

// ---------------------------------------------------------------------------
// K0: conv2d 3x3 same, 2 -> 32, writes g_x
// ---------------------------------------------------------------------------
__global__ void conv_in_kernel(const float* __restrict__ y,
                               const float* __restrict__ w3) {
    __shared__ float ws[576];
    for (int i = threadIdx.x; i < 576; i += blockDim.x) ws[i] = w3[i];
    __syncthreads();

    int idx = blockIdx.x * blockDim.x + threadIdx.x;
    if (idx >= BB * HW) return;
    int b = idx / HW, pix = idx - b * HW;
    int py = pix / WW, px = pix - py * WW;

    float in[2][3][3];
#pragma unroll
    for (int ic = 0; ic < 2; ic++)
#pragma unroll
        for (int ky = 0; ky < 3; ky++)
#pragma unroll
            for (int kx = 0; kx < 3; kx++) {
                int yy = py + ky - 1, xx = px + kx - 1;
                bool v = ((unsigned)yy < HH) && ((unsigned)xx < WW);
                in[ic][ky][kx] =
                    v ? __ldg(y + ((size_t)(b * 2 + ic)) * HW + yy * WW + xx)
                      : 0.0f;
            }

    for (int oc = 0; oc < 32; oc++) {
        float a = 0.0f;
#pragma unroll
        for (int ic = 0; ic < 2; ic++)
#pragma unroll
            for (int k = 0; k < 9; k++)
                a += in[ic][k / 3][k % 3] * ws[(oc * 2 + ic) * 9 + k];
        g_x[((size_t)(b * 32 + oc)) * HW + pix] = a;
    }
}

// ---------------------------------------------------------------------------
// Warp-autonomous directional scan. One warp = one (plane, direction) scan.
// Thread `lane` owns lanes s0=7*lane .. s0+6 of the 224-wide cross axis,
// holding h in registers. Neighbor coupling: registers + 2 shfls/step.
// Stage layouts (per stage = 4 arrays x ABYTES):
//   vertical:   array a, floats [j*224 + s]          (coalesced LDS)
//   horizontal: swz(a*ABYTES + s*16) + c*4           (16B/row chunks, swizzled)
// ---------------------------------------------------------------------------
template <bool HOR, bool REV>
__device__ void warp_scan(const float* __restrict__ g1,
                          const float* __restrict__ g2,
                          const float* __restrict__ g3,
                          const float* __restrict__ xp,
                          float* __restrict__ yp, char* sb, uint32_t su,
                          int lane) {
    const float* arr[4] = {g1, g2, g3, xp};

    auto fill = [&](int st, int tg) {
        uint32_t stb = su + (uint32_t)(st * STAGEF * 4);
        if (HOR) {
            int base = REV ? 220 - 4 * tg : 4 * tg;
#pragma unroll
            for (int a = 0; a < 4; a++) {
                const float* src = arr[a] + base;
#pragma unroll
                for (int k = 0; k < 7; k++) {
                    int s = lane + 32 * k;
                    uint32_t off = swz((uint32_t)(a * ABYTES + s * 16));
                    cpa16(stb + off, src + (size_t)s * WW);
                }
            }
        } else {
#pragma unroll
            for (int a = 0; a < 4; a++)
#pragma unroll
                for (int j = 0; j < 4; j++) {
                    int row = REV ? 223 - (4 * tg + j) : 4 * tg + j;
                    const float* src = arr[a] + (size_t)row * WW;
                    uint32_t dst = stb + (uint32_t)(a * ABYTES + j * 224 * 4);
                    cpa16(dst + lane * 16, src + lane * 4);
                    if (lane < 24)
                        cpa16(dst + (32 + lane) * 16, src + (32 + lane) * 4);
                }
        }
        cpa_commit();
    };

    fill(0, 0);
    fill(1, 1);
    fill(2, 2);

    float h[7];
#pragma unroll
    for (int k = 0; k < 7; k++) h[k] = 0.0f;
    const int s0 = 7 * lane;

    for (int tg = 0; tg < NGRP; tg++) {
        int st = tg % NS;
        cpa_waitN();
        __syncwarp();
        char* stp = sb + st * STAGEF * 4;

        float hv[ST][7];
#pragma unroll
        for (int j = 0; j < ST; j++) {
            // edge h from neighbor threads (previous step's state)
            float hl = __shfl_up_sync(0xffffffffu, h[6], 1);
            float hr = __shfl_down_sync(0xffffffffu, h[0], 1);
            if (lane == 0) hl = 0.0f;
            if (lane == 31) hr = 0.0f;

            float hn[7];
#pragma unroll
            for (int k = 0; k < 7; k++) {
                int s = s0 + k;
                float G1, G2, G3, X;
                if (HOR) {
                    int cc = REV ? 3 - j : j;
                    uint32_t o0 = swz((uint32_t)(0 * ABYTES + s * 16)) + cc * 4;
                    uint32_t o1 = swz((uint32_t)(1 * ABYTES + s * 16)) + cc * 4;
                    uint32_t o2 = swz((uint32_t)(2 * ABYTES + s * 16)) + cc * 4;
                    uint32_t o3 = swz((uint32_t)(3 * ABYTES + s * 16)) + cc * 4;
                    G1 = *(const float*)(stp + o0);
                    G2 = *(const float*)(stp + o1);
                    G3 = *(const float*)(stp + o2);
                    X = *(const float*)(stp + o3);
                } else {
                    const float* f = (const float*)stp;
                    G1 = f[j * 224 + s];
                    G2 = f[896 + j * 224 + s];
                    G3 = f[2 * 896 + j * 224 + s];
                    X = f[3 * 896 + j * 224 + s];
                }
                float inv = __fdividef(
                    1.0f, fmaxf(fabsf(G1) + fabsf(G2) + fabsf(G3), 1.0f));
                float a1 = G1 * inv, a2 = G2 * inv, a3 = G3 * inv;
                float cx = (1.0f - a1 - a2 - a3) * X;
                float l = (k == 0) ? hl : h[k - 1];
                float r = (k == 6) ? hr : h[k + 1];
                hn[k] = fmaf(a1, l, fmaf(a2, h[k], fmaf(a3, r, cx)));
            }
#pragma unroll
            for (int k = 0; k < 7; k++) {
                h[k] = hn[k];
                hv[j][k] = hn[k];
            }
            if (!HOR) {
                int row = REV ? 223 - (4 * tg + j) : 4 * tg + j;
                float* op = yp + (size_t)row * WW + s0;
#pragma unroll
                for (int k = 0; k < 7; k++) op[k] = hn[k];
            }
        }
        if (HOR) {
            int base = REV ? 220 - 4 * tg : 4 * tg;
#pragma unroll
            for (int k = 0; k < 7; k++) {
                float4 o;
                if (REV) {
                    o.x = hv[3][k]; o.y = hv[2][k];
                    o.z = hv[1][k]; o.w = hv[0][k];
                } else {
                    o.x = hv[0][k]; o.y = hv[1][k];
                    o.z = hv[2][k]; o.w = hv[3][k];
                }
                *(float4*)(yp + (size_t)(s0 + k) * WW + base) = o;
            }
        }

        if (tg + NS < NGRP) {
            fill(st, tg + NS);
        } else {
            cpa_commit();  // keep per-thread group counts aligned
        }
    }
}

// ---------------------------------------------------------------------------
// Scan kernel: grid = 128 planes, block = 128 threads (4 warps = 4 dirs).
// d: 0=lr (W fwd), 1=rl (H rev), 2=du (H fwd), 3=ud (W rev);
// direction d uses gate channel groups 3d..3d+2 (matches reference).
// ---------------------------------------------------------------------------
__global__ void __launch_bounds__(128) scan_kernel(
    const float* __restrict__ gates) {
    extern __shared__ __align__(128) char smem[];

    int lane = threadIdx.x & 31;
    int d = threadIdx.x >> 5;  // warp = direction
    int plane = blockIdx.x;
    int b = plane >> 5, c = plane & 31;

    const float* g1 =
        gates + ((size_t)(b * 384 + (3 * d + 0) * 32 + c)) * HW;
    const float* g2 =
        gates + ((size_t)(b * 384 + (3 * d + 1) * 32 + c)) * HW;
    const float* g3 =
        gates + ((size_t)(b * 384 + (3 * d + 2) * 32 + c)) * HW;
    const float* xp = g_x + (size_t)plane * HW;
    float* yp = g_dir + (size_t)d * NTOT + (size_t)plane * HW;

    char* sb = smem + (size_t)d * WARPF * 4;
    uint32_t su = s2u(sb);

    switch (d) {
        case 0:  warp_scan<true,  false>(g1, g2, g3, xp, yp, sb, su, lane); break;
        case 1:  warp_scan<false, true >(g1, g2, g3, xp, yp, sb, su, lane); break;
        case 2:  warp_scan<false, false>(g1, g2, g3, xp, yp, sb, su, lane); break;
        default: warp_scan<true,  true >(g1, g2, g3, xp, yp, sb, su, lane); break;
    }
}

// ---------------------------------------------------------------------------
// Combine: g_x = elementwise max over the 4 direction buffers (float4).
// ---------------------------------------------------------------------------
__global__ void combine_kernel() {
    const size_t n4 = NTOT / 4;
    const float4* p0 = (const float4*)g_dir;
    const float4* p1 = (const float4*)(g_dir + NTOT);
    const float4* p2 = (const float4*)(g_dir + 2 * NTOT);
    const float4* p3 = (const float4*)(g_dir + 3 * NTOT);
    float4* o = (float4*)g_x;
    for (size_t i = blockIdx.x * (size_t)blockDim.x + threadIdx.x; i < n4;
         i += (size_t)gridDim.x * blockDim.x) {
        float4 a = __ldg(p0 + i), b = __ldg(p1 + i);
        float4 c = __ldg(p2 + i), d = __ldg(p3 + i);
        float4 r;
        r.x = fmaxf(fmaxf(a.x, b.x), fmaxf(c.x, d.x));
        r.y = fmaxf(fmaxf(a.y, b.y), fmaxf(c.y, d.y));
        r.z = fmaxf(fmaxf(a.z, b.z), fmaxf(c.z, d.z));
        r.w = fmaxf(fmaxf(a.w, b.w), fmaxf(c.w, d.w));
        o[i] = r;
    }
}

// ---------------------------------------------------------------------------
// K3: conv2d 3x3 same 32 -> 2 on g_x, fused log_softmax over the 2 channels.
// ---------------------------------------------------------------------------
__global__ void conv_out_kernel(const float* __restrict__ w4,
                                float* __restrict__ out) {
    __shared__ float ws[576];
    for (int i = threadIdx.x; i < 576; i += blockDim.x) ws[i] = w4[i];
    __syncthreads();

    int idx = blockIdx.x * blockDim.x + threadIdx.x;
    if (idx >= BB * HW) return;
    int b = idx / HW, pix = idx - b * HW;
    int py = pix / WW, px = pix - py * WW;

    float a0 = 0.0f, a1 = 0.0f;
    for (int ic = 0; ic < 32; ic++) {
        const float* ip = g_x + ((size_t)(b * 32 + ic)) * HW;
#pragma unroll
        for (int ky = 0; ky < 3; ky++) {
            int yy = py + ky - 1;
            bool vy = (unsigned)yy < HH;
#pragma unroll
            for (int kx = 0; kx < 3; kx++) {
                int xx = px + kx - 1;
                float v = (vy && (unsigned)xx < WW)
                              ? __ldg(ip + yy * WW + xx)
                              : 0.0f;
                int wi = ic * 9 + ky * 3 + kx;
                a0 += v * ws[wi];
                a1 += v * ws[288 + wi];
            }
        }
    }
    float m = fmaxf(a0, a1);
    float l = m + logf(expf(a0 - m) + expf(a1 - m));
    out[(size_t)(b * 2) * HW + pix] = a0 - l;
    out[(size_t)(b * 2 + 1) * HW + pix] = a1 - l;
}

// ---------------------------------------------------------------------------
// Launch: K0 -> scan(pass1) -> combine -> scan(pass2) -> combine -> K3
// ---------------------------------------------------------------------------
extern "C" void kernel_launch(void* const* d_in, const int* in_sizes, int n_in,
                              void* d_out, int out_size) {
    const float* gates = (const float*)d_in[0];
    const float* y     = (const float*)d_in[1];
    const float* w3    = (const float*)d_in[2];
    const float* w4    = (const float*)d_in[3];
    float* out = (float*)d_out;

    cudaFuncSetAttribute(scan_kernel,
                         cudaFuncAttributeMaxDynamicSharedMemorySize,
                         SMEM_BYTES);

    int pxblocks = (BB * HW + 255) / 256;

    conv_in_kernel<<<pxblocks, 256>>>(y, w3);
    scan_kernel<<<NPLANE, 128, SMEM_BYTES>>>(gates);
    combine_kernel<<<2048, 256>>>();
    scan_kernel<<<NPLANE, 128, SMEM_BYTES>>>(gates);
    combine_kernel<<<2048, 256>>>();
    conv_out_kernel<<<pxblocks, 256>>>(w4, out);
}